// round 3
// baseline (speedup 1.0000x reference)
#include <cuda_runtime.h>
#include <cuda_bf16.h>
#include <cstdint>

// GRU: B=64, S=512, I=256, H=1024, O=256.
// Pipeline:
//   1) transpose_kernel: WTzr[2048][1024] (cols of [Whz|Whr]), WThh[1024][1024]
//   2) xproj_kernel: XP[b*512+s][3072] = x_bs @ [Wxz|Wxr|Wxh] + [bz|br|bh]
//   3) gru_kernel (persistent, 128 blocks, software grid barrier):
//        per step: phase A -> z (sigmoid) and rh = r*h   (cols 0..2047)
//                  phase B -> n (tanh), h_new = (1-z)h + z n
//      h, z, rh stored transposed [k][b] so batch dim is contiguous (float4).
//   4) head_kernel: out = h_final @ Wf + bf

#define NBLK 128
#define NTHR 256
#define Bv 64
#define Sv 512
#define Iv 256
#define Hv 1024
#define Ov 256

// -------- device scratch (static allocations are allowed) --------
__device__ float d_XP[(size_t)Bv * Sv * 3072];   // 402 MB: x-projections (+bias)
__device__ float d_WTzr[2048 * 1024];            // transposed [col][k] of [Whz|Whr]
__device__ float d_WThh[1024 * 1024];            // transposed [col][k] of Whh
__device__ float d_hT[2][Hv * Bv];               // h transposed [k][b], double buffered
__device__ float d_zT[Hv * Bv];                  // z transposed [j][b]
__device__ float d_rhT[Hv * Bv];                 // (r*h) transposed [k][b]
__device__ unsigned d_count;                      // grid barrier arrivals
__device__ unsigned d_gen;                        // grid barrier generation (monotone)

typedef unsigned long long u64;

// -------- f32x2 helpers (Blackwell packed fp32) --------
__device__ __forceinline__ u64 dup2(float x) {
    u64 r; asm("mov.b64 %0, {%1, %1};" : "=l"(r) : "f"(x)); return r;
}
__device__ __forceinline__ void fma2(u64& a, u64 x, u64 y) {
    asm("fma.rn.f32x2 %0, %1, %2, %0;" : "+l"(a) : "l"(x), "l"(y));
}
__device__ __forceinline__ void add2(u64& a, u64 x) {
    asm("add.rn.f32x2 %0, %1, %0;" : "+l"(a) : "l"(x));
}
__device__ __forceinline__ float2 unp2(u64 v) {
    float2 f; asm("mov.b64 {%0, %1}, %2;" : "=f"(f.x), "=f"(f.y) : "l"(v)); return f;
}
// one LDS.128 -> two packed f32x2
__device__ __forceinline__ void lds128(u64& a, u64& b, unsigned addr) {
    asm volatile("ld.shared.v2.u64 {%0, %1}, [%2];" : "=l"(a), "=l"(b) : "r"(addr));
}

// -------- software grid barrier (all NBLK blocks co-resident) --------
__device__ __forceinline__ void gridbar() {
    __syncthreads();
    if (threadIdx.x == 0) {
        __threadfence();
        volatile unsigned* vg = &d_gen;
        unsigned g = *vg;
        if (atomicAdd(&d_count, 1u) == NBLK - 1) {
            d_count = 0;
            __threadfence();
            *vg = g + 1;
        } else {
            while (*vg == g) { __nanosleep(64); }
        }
        __threadfence();
    }
    __syncthreads();
}

// -------- weight transpose --------
__global__ void transpose_kernel(const float* __restrict__ Whz,
                                 const float* __restrict__ Whr,
                                 const float* __restrict__ Whh) {
    int rowid = blockIdx.x;  // 0..3071
    const float* src; float* dst; int col;
    if (rowid < 1024)       { src = Whz; col = rowid;        dst = &d_WTzr[(size_t)rowid * 1024]; }
    else if (rowid < 2048)  { src = Whr; col = rowid - 1024; dst = &d_WTzr[(size_t)rowid * 1024]; }
    else                    { src = Whh; col = rowid - 2048; dst = &d_WThh[(size_t)(rowid - 2048) * 1024]; }
    for (int k = threadIdx.x; k < 1024; k += blockDim.x)
        dst[k] = src[(size_t)k * 1024 + col];
}

// -------- x-projection GEMM: XP[row][3072], row = b*512+s --------
// grid (48, 512): blockIdx.x = 64-col tile, blockIdx.y = 64-row tile.
__global__ void __launch_bounds__(256) xproj_kernel(
    const float* __restrict__ x,
    const float* __restrict__ Wxz, const float* __restrict__ Wxr, const float* __restrict__ Wxh,
    const float* __restrict__ bz,  const float* __restrict__ br,  const float* __restrict__ bh) {
    __shared__ float As[64 * 68];
    __shared__ float Bs[64 * 68];
    const int tid = threadIdx.x;
    const int ct = blockIdx.x, rt = blockIdx.y;
    const int wsel = ct >> 4;
    const float* W    = (wsel == 0) ? Wxz : ((wsel == 1) ? Wxr : Wxh);
    const float* bias = (wsel == 0) ? bz  : ((wsel == 1) ? br  : bh);
    const int colbase = (ct & 15) * 64;
    const int row0 = rt * 64;
    const int r4 = (tid >> 4) * 4, c4 = (tid & 15) * 4;

    u64 acc[4][2] = {};
    for (int k0 = 0; k0 < 256; k0 += 64) {
        __syncthreads();
#pragma unroll
        for (int i = 0; i < 4; i++) {
            int q = tid + i * 256; int rr = q >> 4, kq = q & 15;
            *(float4*)&As[rr * 68 + kq * 4] =
                *(const float4*)&x[(size_t)(row0 + rr) * 256 + k0 + kq * 4];
        }
#pragma unroll
        for (int i = 0; i < 4; i++) {
            int q = tid + i * 256; int kk = q >> 4, cq = q & 15;
            *(float4*)&Bs[kk * 68 + cq * 4] =
                *(const float4*)&W[(size_t)(k0 + kk) * 1024 + colbase + cq * 4];
        }
        __syncthreads();
        unsigned bs_u = (unsigned)__cvta_generic_to_shared(&Bs[c4]);
#pragma unroll 8
        for (int kk = 0; kk < 64; kk++) {
            u64 bLo, bHi; lds128(bLo, bHi, bs_u + kk * 68 * 4);
#pragma unroll
            for (int i = 0; i < 4; i++) {
                u64 ad = dup2(As[(r4 + i) * 68 + kk]);
                fma2(acc[i][0], ad, bLo);
                fma2(acc[i][1], ad, bHi);
            }
        }
    }
    float4 bb = *(const float4*)&bias[colbase + c4];
#pragma unroll
    for (int i = 0; i < 4; i++) {
        float2 lo = unp2(acc[i][0]), hi = unp2(acc[i][1]);
        float4 o = make_float4(lo.x + bb.x, lo.y + bb.y, hi.x + bb.z, hi.y + bb.w);
        *(float4*)&d_XP[(size_t)(row0 + r4 + i) * 3072 + ct * 64 + c4] = o;
    }
}

// -------- persistent GRU recurrence --------
// smem: hs[2][128][68] (K-chunk of h or rh, [k][b]), ws[2][16][132] (weights [c][k]),
//       red[128][4] (K-split reduction).
#define HS_F (2 * 128 * 68)
#define WS_F (2 * 16 * 132)
#define SMEM_BYTES ((HS_F + WS_F) * 4 + 128 * 4 * 8)

__global__ void __launch_bounds__(NTHR, 1) gru_kernel() {
    extern __shared__ float sm[];
    float* hs = sm;
    float* ws = sm + HS_F;
    u64*   red = (u64*)(ws + WS_F);

    const int tid = threadIdx.x, bid = blockIdx.x;
    // decomposition shared by both phases:
    const int c2 = tid & 7;            // col (pair) index within block
    const int g  = (tid >> 3) & 15;    // batch group (4 batches)
    const int kh = tid >> 7;           // K-split half
    const int b0 = g * 4;
    const int cc0 = bid * 16;          // phase A: 16 cols (z|r space, 0..2047)
    const int cA = cc0 + 2 * c2, cB = cA + 1;
    const int jB = bid * 8 + c2;       // phase B: 8 cols (n space, 0..1023)

    const unsigned hs_u = (unsigned)__cvta_generic_to_shared(hs);

    for (int s = 0; s < Sv; s++) {
        const int par = s & 1;
        const float* hOld = d_hT[par];

        // ================= Phase A: z and r*h =================
        u64 acA01 = 0, acA23 = 0, acB01 = 0, acB23 = 0;
        if (s > 0) {
            for (int t = 0; t < 4; t++) {
                __syncthreads();
                // stage h chunks for both K-halves: [half][128][64]
#pragma unroll
                for (int i = 0; i < 16; i++) {
                    int q = tid + i * NTHR;          // 0..4095 float4 slots
                    int half = q >> 11; int rem = q & 2047;
                    int kk = rem >> 4;  int bq = rem & 15;
                    int kg = half * 512 + t * 128 + kk;
                    float4 v = __ldcg((const float4*)&hOld[kg * 64 + bq * 4]);
                    *(float4*)&hs[(half * 128 + kk) * 68 + bq * 4] = v;
                }
                // stage weights: ws[half][16 cols][128 k]
#pragma unroll
                for (int i = 0; i < 4; i++) {
                    int q = tid + i * NTHR;          // 0..1023
                    int half = q >> 9; int rem = q & 511;
                    int cr = rem >> 5; int kq = rem & 31;
                    int kg = half * 512 + t * 128 + kq * 4;
                    float4 v = *(const float4*)&d_WTzr[(size_t)(cc0 + cr) * 1024 + kg];
                    *(float4*)&ws[(half * 16 + cr) * 132 + kq * 4] = v;
                }
                __syncthreads();
                const float* wA = &ws[(kh * 16 + 2 * c2) * 132];
                const unsigned hb_u = hs_u + ((kh * 128) * 68 + b0) * 4;
#pragma unroll 8
                for (int kk = 0; kk < 128; kk += 4) {
                    float4 wa4 = *(const float4*)(wA + kk);
                    float4 wb4 = *(const float4*)(wA + 132 + kk);
#pragma unroll
                    for (int j = 0; j < 4; j++) {
                        u64 h01, h23; lds128(h01, h23, hb_u + (kk + j) * 68 * 4);
                        u64 wad = dup2(((const float*)&wa4)[j]);
                        u64 wbd = dup2(((const float*)&wb4)[j]);
                        fma2(acA01, h01, wad); fma2(acA23, h23, wad);
                        fma2(acB01, h01, wbd); fma2(acB23, h23, wbd);
                    }
                }
            }
        }
        __syncthreads();
        if (kh == 1) {
            u64* r = &red[(tid - 128) * 4];
            r[0] = acA01; r[1] = acA23; r[2] = acB01; r[3] = acB23;
        }
        __syncthreads();
        if (kh == 0) {
            add2(acA01, red[tid * 4 + 0]); add2(acA23, red[tid * 4 + 1]);
            add2(acB01, red[tid * 4 + 2]); add2(acB23, red[tid * 4 + 3]);
            float a4[4], bb4[4];
            { float2 f = unp2(acA01); a4[0] = f.x; a4[1] = f.y;
              f = unp2(acA23); a4[2] = f.x; a4[3] = f.y;
              f = unp2(acB01); bb4[0] = f.x; bb4[1] = f.y;
              f = unp2(acB23); bb4[2] = f.x; bb4[3] = f.y; }
            float sA[4], sB[4];
#pragma unroll
            for (int i = 0; i < 4; i++) {
                int b = b0 + i;
                size_t row = (size_t)(b * Sv + s) * 3072;
                float vA = a4[i]  + __ldg(&d_XP[row + cA]);
                float vB = bb4[i] + __ldg(&d_XP[row + cB]);
                sA[i] = 1.f / (1.f + __expf(-vA));
                sB[i] = 1.f / (1.f + __expf(-vB));
            }
            if (cA < 1024) {
                *(float4*)&d_zT[cA * 64 + b0] = make_float4(sA[0], sA[1], sA[2], sA[3]);
                *(float4*)&d_zT[cB * 64 + b0] = make_float4(sB[0], sB[1], sB[2], sB[3]);
            } else {
                int ja = cA - 1024, jb = cB - 1024;
                float4 hA = make_float4(0.f, 0.f, 0.f, 0.f), hB = hA;
                if (s > 0) {
                    hA = __ldcg((const float4*)&hOld[ja * 64 + b0]);
                    hB = __ldcg((const float4*)&hOld[jb * 64 + b0]);
                }
                *(float4*)&d_rhT[ja * 64 + b0] =
                    make_float4(sA[0] * hA.x, sA[1] * hA.y, sA[2] * hA.z, sA[3] * hA.w);
                *(float4*)&d_rhT[jb * 64 + b0] =
                    make_float4(sB[0] * hB.x, sB[1] * hB.y, sB[2] * hB.z, sB[3] * hB.w);
            }
        }
        gridbar();

        // ================= Phase B: n and h update =================
        u64 ac01 = 0, ac23 = 0;
        if (s > 0) {
            for (int t = 0; t < 4; t++) {
                __syncthreads();
#pragma unroll
                for (int i = 0; i < 16; i++) {
                    int q = tid + i * NTHR;
                    int half = q >> 11; int rem = q & 2047;
                    int kk = rem >> 4;  int bq = rem & 15;
                    int kg = half * 512 + t * 128 + kk;
                    float4 v = __ldcg((const float4*)&d_rhT[kg * 64 + bq * 4]);
                    *(float4*)&hs[(half * 128 + kk) * 68 + bq * 4] = v;
                }
#pragma unroll
                for (int i = 0; i < 2; i++) {
                    int q = tid + i * NTHR;          // 0..511
                    int half = q >> 8; int rem = q & 255;
                    int cr = rem >> 5; int kq = rem & 31;
                    int kg = half * 512 + t * 128 + kq * 4;
                    float4 v = *(const float4*)&d_WThh[(size_t)(bid * 8 + cr) * 1024 + kg];
                    *(float4*)&ws[(half * 8 + cr) * 132 + kq * 4] = v;
                }
                __syncthreads();
                const float* wp = &ws[(kh * 8 + c2) * 132];
                const unsigned hb_u = hs_u + ((kh * 128) * 68 + b0) * 4;
#pragma unroll 8
                for (int kk = 0; kk < 128; kk += 4) {
                    float4 w4 = *(const float4*)(wp + kk);
#pragma unroll
                    for (int j = 0; j < 4; j++) {
                        u64 h01, h23; lds128(h01, h23, hb_u + (kk + j) * 68 * 4);
                        u64 wd = dup2(((const float*)&w4)[j]);
                        fma2(ac01, h01, wd); fma2(ac23, h23, wd);
                    }
                }
            }
        }
        __syncthreads();
        if (kh == 1) {
            u64* r = &red[(tid - 128) * 4];
            r[0] = ac01; r[1] = ac23;
        }
        __syncthreads();
        if (kh == 0) {
            add2(ac01, red[tid * 4 + 0]); add2(ac23, red[tid * 4 + 1]);
            float n4[4];
            { float2 f = unp2(ac01); n4[0] = f.x; n4[1] = f.y;
              f = unp2(ac23); n4[2] = f.x; n4[3] = f.y; }
            float4 z4 = __ldcg((const float4*)&d_zT[jB * 64 + b0]);
            float4 h4 = make_float4(0.f, 0.f, 0.f, 0.f);
            if (s > 0) h4 = __ldcg((const float4*)&hOld[jB * 64 + b0]);
            float outv[4];
#pragma unroll
            for (int i = 0; i < 4; i++) {
                int b = b0 + i;
                size_t row = (size_t)(b * Sv + s) * 3072;
                float v = n4[i] + __ldg(&d_XP[row + 2048 + jB]);
                float n = tanhf(v);
                float z = ((const float*)&z4)[i];
                float h = ((const float*)&h4)[i];
                outv[i] = (1.f - z) * h + z * n;
            }
            *(float4*)&d_hT[par ^ 1][jB * 64 + b0] =
                make_float4(outv[0], outv[1], outv[2], outv[3]);
        }
        gridbar();
    }
}

// -------- head: out[b][o] = sum_k hT[0][k][b] * Wf[k][o] + bf[o] --------
__global__ void head_kernel(const float* __restrict__ Wf,
                            const float* __restrict__ bf,
                            float* __restrict__ out) {
    const int b = blockIdx.x, o = threadIdx.x;
    const float* h = d_hT[0];   // after 512 steps, final h lives in buffer 0
    float acc = bf[o];
#pragma unroll 8
    for (int k = 0; k < 1024; k++)
        acc += h[k * 64 + b] * Wf[(size_t)k * 256 + o];
    out[b * 256 + o] = acc;
}

extern "C" void kernel_launch(void* const* d_in, const int* in_sizes, int n_in,
                              void* d_out, int out_size) {
    const float* x   = (const float*)d_in[0];
    const float* Wxz = (const float*)d_in[1];
    const float* Whz = (const float*)d_in[2];
    const float* Wxr = (const float*)d_in[3];
    const float* Whr = (const float*)d_in[4];
    const float* Wxh = (const float*)d_in[5];
    const float* Whh = (const float*)d_in[6];
    const float* bz  = (const float*)d_in[7];
    const float* br  = (const float*)d_in[8];
    const float* bh  = (const float*)d_in[9];
    const float* Wf  = (const float*)d_in[10];
    const float* bf  = (const float*)d_in[11];
    float* out = (float*)d_out;

    transpose_kernel<<<3072, 256>>>(Whz, Whr, Whh);
    dim3 gx(48, 512);
    xproj_kernel<<<gx, 256>>>(x, Wxz, Wxr, Wxh, bz, br, bh);
    cudaFuncSetAttribute(gru_kernel, cudaFuncAttributeMaxDynamicSharedMemorySize, SMEM_BYTES);
    gru_kernel<<<NBLK, NTHR, SMEM_BYTES>>>();
    head_kernel<<<64, 256>>>(Wf, bf, out);
}

// round 4
// speedup vs baseline: 1.5086x; 1.5086x over previous
#include <cuda_runtime.h>
#include <cstdint>

// GRU: B=64, S=512, I=256, H=1024, O=256.
//   1) xproj_kernel: XP[b*512+s][3072] = x_bs @ [Wxz|Wxr|Wxh] + [bz|br|bh]
//   2) gru_kernel (persistent, 128 blocks, monotone-counter grid barrier):
//        phase A -> z = sigmoid(.) (blocks 0-63), rh = sigmoid(.)*h (blocks 64-127)
//        phase B -> n = tanh(.), h_new = (1-z)h + z n
//      Weights resident in smem (96KB, native [k][col] layout -> col-pairs
//      pre-packed for fma.rn.f32x2). h/rh chunks double-buffered through smem.
//   3) head_kernel: out = h_final @ Wf + bf

#define NBLK 128
#define NTHR 256
#define Bv 64
#define Sv 512
#define Hv 1024

typedef unsigned long long u64;

// -------- device scratch --------
__device__ float d_XP[(size_t)Bv * Sv * 3072];   // 402 MB x-projections (+bias)
__device__ float d_hT[2][Hv * Bv];               // h transposed [k][b], double buffered
__device__ float d_zT[Hv * Bv];                  // z transposed [j][b]
__device__ float d_rhT[Hv * Bv];                 // (r*h) transposed [k][b]
__device__ unsigned d_count;                      // monotone barrier counter

// -------- f32x2 helpers --------
__device__ __forceinline__ u64 dup2(float x) {
    u64 r; asm("mov.b64 %0, {%1, %1};" : "=l"(r) : "f"(x)); return r;
}
__device__ __forceinline__ void fma2(u64& a, u64 x, u64 y) {
    asm("fma.rn.f32x2 %0, %1, %2, %0;" : "+l"(a) : "l"(x), "l"(y));
}
__device__ __forceinline__ void add2(u64& a, u64 x) {
    asm("add.rn.f32x2 %0, %1, %0;" : "+l"(a) : "l"(x));
}
__device__ __forceinline__ float2 unp2(u64 v) {
    float2 f; asm("mov.b64 {%0, %1}, %2;" : "=f"(f.x), "=f"(f.y) : "l"(v)); return f;
}
__device__ __forceinline__ void lds128(u64& a, u64& b, unsigned addr) {
    asm volatile("ld.shared.v2.u64 {%0, %1}, [%2];" : "=l"(a), "=l"(b) : "r"(addr));
}
__device__ __forceinline__ float sigmoidf(float x) { return 1.f / (1.f + __expf(-x)); }

// -------- monotone grid barrier (replay-safe, no reset) --------
__device__ __forceinline__ void gridbar() {
    __syncthreads();
    if (threadIdx.x == 0) {
        __threadfence();
        unsigned a = atomicAdd(&d_count, 1u);
        unsigned target = a - (a & (NBLK - 1)) + NBLK;
        unsigned cur;
        do {
            asm volatile("ld.acquire.gpu.u32 %0, [%1];" : "=r"(cur) : "l"(&d_count));
        } while ((int)(cur - target) < 0);
    }
    __syncthreads();
}

// -------- x-projection GEMM (unchanged from passing R2 kernel) --------
__global__ void __launch_bounds__(256) xproj_kernel(
    const float* __restrict__ x,
    const float* __restrict__ Wxz, const float* __restrict__ Wxr, const float* __restrict__ Wxh,
    const float* __restrict__ bz,  const float* __restrict__ br,  const float* __restrict__ bh) {
    __shared__ float As[64 * 68];
    __shared__ float Bs[64 * 68];
    const int tid = threadIdx.x;
    const int ct = blockIdx.x, rt = blockIdx.y;
    const int wsel = ct >> 4;
    const float* W    = (wsel == 0) ? Wxz : ((wsel == 1) ? Wxr : Wxh);
    const float* bias = (wsel == 0) ? bz  : ((wsel == 1) ? br  : bh);
    const int colbase = (ct & 15) * 64;
    const int row0 = rt * 64;
    const int r4 = (tid >> 4) * 4, c4 = (tid & 15) * 4;

    u64 acc[4][2] = {};
    for (int k0 = 0; k0 < 256; k0 += 64) {
        __syncthreads();
#pragma unroll
        for (int i = 0; i < 4; i++) {
            int q = tid + i * 256; int rr = q >> 4, kq = q & 15;
            *(float4*)&As[rr * 68 + kq * 4] =
                *(const float4*)&x[(size_t)(row0 + rr) * 256 + k0 + kq * 4];
        }
#pragma unroll
        for (int i = 0; i < 4; i++) {
            int q = tid + i * 256; int kk = q >> 4, cq = q & 15;
            *(float4*)&Bs[kk * 68 + cq * 4] =
                *(const float4*)&W[(size_t)(k0 + kk) * 1024 + colbase + cq * 4];
        }
        __syncthreads();
        unsigned bs_u = (unsigned)__cvta_generic_to_shared(&Bs[c4]);
#pragma unroll 8
        for (int kk = 0; kk < 64; kk++) {
            u64 bLo, bHi; lds128(bLo, bHi, bs_u + kk * 68 * 4);
#pragma unroll
            for (int i = 0; i < 4; i++) {
                u64 ad = dup2(As[(r4 + i) * 68 + kk]);
                fma2(acc[i][0], ad, bLo);
                fma2(acc[i][1], ad, bHi);
            }
        }
    }
    float4 bb = *(const float4*)&bias[colbase + c4];
#pragma unroll
    for (int i = 0; i < 4; i++) {
        float2 lo = unp2(acc[i][0]), hi = unp2(acc[i][1]);
        float4 o = make_float4(lo.x + bb.x, lo.y + bb.y, hi.x + bb.z, hi.y + bb.w);
        *(float4*)&d_XP[(size_t)(row0 + r4 + i) * 3072 + ct * 64 + c4] = o;
    }
}

// -------- GEMM phase: stream 1024x64 activations through double-buffered smem --------
// COLS: weight row width (16 for phase A, 8 for B). KPT: k per thread per chunk.
template<int COLS, int KPT>
__device__ __forceinline__ void gemm_phase(
    const float* __restrict__ src,   // [1024][64] in global (ldcg)
    unsigned ws_su,                  // shared addr of weight tile base
    float* __restrict__ hbuf,        // shared, 2 x 8192 floats
    int tid, int kq, int cg, int b0,
    u64 acc01[4], u64 acc23[4])
{
    float4 rg[8];
#pragma unroll
    for (int i = 0; i < 8; i++) {
        int q = tid + i * NTHR;
        rg[i] = __ldcg((const float4*)&src[(q >> 4) * 64 + (q & 15) * 4]);
    }
#pragma unroll
    for (int i = 0; i < 8; i++) {
        int q = tid + i * NTHR;
        *(float4*)&hbuf[(q >> 4) * 64 + (q & 15) * 4] = rg[i];
    }
    __syncthreads();
#pragma unroll 1
    for (int t = 0; t < 8; t++) {
        if (t < 7) {
            const float* sp = src + (t + 1) * 128 * 64;
#pragma unroll
            for (int i = 0; i < 8; i++) {
                int q = tid + i * NTHR;
                rg[i] = __ldcg((const float4*)&sp[(q >> 4) * 64 + (q & 15) * 4]);
            }
        }
        unsigned wb = ws_su + (unsigned)(((t * 128 + kq * KPT) * COLS + cg * 4) * 4);
        const float4* hp = (const float4*)(hbuf + (t & 1) * 8192 + kq * KPT * 64 + b0);
#pragma unroll
        for (int j = 0; j < KPT; j++) {
            u64 w01, w23;
            lds128(w01, w23, wb + j * COLS * 4);
            float4 h4 = hp[j * 16];
            u64 hd;
            hd = dup2(h4.x); fma2(acc01[0], w01, hd); fma2(acc23[0], w23, hd);
            hd = dup2(h4.y); fma2(acc01[1], w01, hd); fma2(acc23[1], w23, hd);
            hd = dup2(h4.z); fma2(acc01[2], w01, hd); fma2(acc23[2], w23, hd);
            hd = dup2(h4.w); fma2(acc01[3], w01, hd); fma2(acc23[3], w23, hd);
        }
        if (t < 7) {
            float* db = hbuf + ((t + 1) & 1) * 8192;
#pragma unroll
            for (int i = 0; i < 8; i++) {
                int q = tid + i * NTHR;
                *(float4*)&db[(q >> 4) * 64 + (q & 15) * 4] = rg[i];
            }
        }
        __syncthreads();
    }
}

// -------- persistent GRU recurrence --------
// smem: wsA[1024][16] (64KB), wsB[1024][8] (32KB), hbuf[2][8192] (64KB), red[2048] u64 (16KB)
#define SMEM_BYTES ((16384 + 8192 + 16384) * 4 + 2048 * 8)

__global__ void __launch_bounds__(NTHR, 1) gru_kernel(
    const float* __restrict__ Whz, const float* __restrict__ Whr,
    const float* __restrict__ Whh)
{
    extern __shared__ float sm[];
    float* wsA  = sm;                    // [1024][16]
    float* wsB  = sm + 16384;            // [1024][8]
    float* hbuf = sm + 16384 + 8192;     // [2][8192]
    u64*   red  = (u64*)(sm + 16384 + 8192 + 16384);

    const int tid = threadIdx.x, bid = blockIdx.x;
    const unsigned wsA_su = (unsigned)__cvta_generic_to_shared(wsA);
    const unsigned wsB_su = (unsigned)__cvta_generic_to_shared(wsB);

    // ---- load block's weight slices into smem once (native [k][col] layout) ----
    const float* WA = (bid < 64) ? (Whz + bid * 16) : (Whr + (bid - 64) * 16);
#pragma unroll
    for (int i = 0; i < 16; i++) {
        int q = tid + i * NTHR; int k = q >> 2, c = q & 3;
        *(float4*)&wsA[k * 16 + c * 4] = __ldg((const float4*)&WA[(size_t)k * 1024 + c * 4]);
    }
#pragma unroll
    for (int i = 0; i < 8; i++) {
        int q = tid + i * NTHR; int k = q >> 1, c = q & 1;
        *(float4*)&wsB[k * 8 + c * 4] = __ldg((const float4*)&Whh[(size_t)k * 1024 + bid * 8 + c * 4]);
    }

    // ---- zero h0 across the grid ----
    ((float2*)d_hT[0])[bid * NTHR + tid] = make_float2(0.f, 0.f);
    gridbar();

    // thread mappings
    const int kqA = tid >> 6, cgA = (tid >> 4) & 3;
    const int g = tid & 15, b0 = g * 4;
    const int kqB = tid >> 5, cgB = (tid >> 4) & 1;
    // epilogue A: two consecutive b for col-pair
    const int ecpA = tid >> 5;              // col-pair 0..7
    const int ebA  = (tid * 2) & 63;        // even b
    const int cA0  = bid * 16 + ecpA * 2;   // global col in [0,2048)
    // epilogue B
    const int ecpB = tid >> 6;              // 0..3
    const int ebB  = tid & 63;
    const int jB0  = bid * 8 + ecpB * 2;

    for (int s = 0; s < Sv; s++) {
        const float* hsrc = d_hT[s & 1];
        float* hdst = d_hT[(s & 1) ^ 1];

        // ================= Phase A =================
        // prefetch epilogue operands
        float2 xpA0 = __ldg((const float2*)&d_XP[((size_t)ebA * 512 + s) * 3072 + cA0]);
        float2 xpA1 = __ldg((const float2*)&d_XP[((size_t)(ebA + 1) * 512 + s) * 3072 + cA0]);
        float2 hA0 = make_float2(0.f, 0.f), hA1 = hA0;
        if (bid >= 64) {
            hA0 = __ldcg((const float2*)&hsrc[(cA0 - 1024) * 64 + ebA]);
            hA1 = __ldcg((const float2*)&hsrc[(cA0 - 1023) * 64 + ebA]);
        }

        u64 a01[4] = {0, 0, 0, 0}, a23[4] = {0, 0, 0, 0};
        gemm_phase<16, 32>(hsrc, wsA_su, hbuf, tid, kqA, cgA, b0, a01, a23);

        {
            u64* rp = red + kqA * 512 + (cgA * 2) * 64 + b0;
#pragma unroll
            for (int bj = 0; bj < 4; bj++) { rp[bj] = a01[bj]; rp[64 + bj] = a23[bj]; }
        }
        __syncthreads();
        {
            int idx = tid * 2;
            u64 s0 = red[idx], s1 = red[idx + 1];
#pragma unroll
            for (int p = 1; p < 4; p++) {
                add2(s0, red[p * 512 + idx]);
                add2(s1, red[p * 512 + idx + 1]);
            }
            float2 f0 = unp2(s0), f1 = unp2(s1);  // f0: (c0,c1) @ b=ebA ; f1: @ b=ebA+1
            float v00 = sigmoidf(f0.x + xpA0.x), v01 = sigmoidf(f0.y + xpA0.y);
            float v10 = sigmoidf(f1.x + xpA1.x), v11 = sigmoidf(f1.y + xpA1.y);
            if (bid < 64) {
                *(float2*)&d_zT[cA0 * 64 + ebA]       = make_float2(v00, v10);
                *(float2*)&d_zT[(cA0 + 1) * 64 + ebA] = make_float2(v01, v11);
            } else {
                int j0 = cA0 - 1024;
                *(float2*)&d_rhT[j0 * 64 + ebA]       = make_float2(v00 * hA0.x, v10 * hA0.y);
                *(float2*)&d_rhT[(j0 + 1) * 64 + ebA] = make_float2(v01 * hA1.x, v11 * hA1.y);
            }
        }
        gridbar();

        // ================= Phase B =================
        float2 xpB = __ldg((const float2*)&d_XP[((size_t)ebB * 512 + s) * 3072 + 2048 + jB0]);
        float z0 = __ldcg(&d_zT[jB0 * 64 + ebB]);
        float z1 = __ldcg(&d_zT[(jB0 + 1) * 64 + ebB]);
        float h0 = __ldcg(&hsrc[jB0 * 64 + ebB]);
        float h1 = __ldcg(&hsrc[(jB0 + 1) * 64 + ebB]);

        u64 n01[4] = {0, 0, 0, 0}, n23[4] = {0, 0, 0, 0};
        gemm_phase<8, 16>(d_rhT, wsB_su, hbuf, tid, kqB, cgB, b0, n01, n23);

        {
            u64* rp = red + kqB * 256 + (cgB * 2) * 64 + b0;
#pragma unroll
            for (int bj = 0; bj < 4; bj++) { rp[bj] = n01[bj]; rp[64 + bj] = n23[bj]; }
        }
        __syncthreads();
        {
            u64 ss = red[tid];
#pragma unroll
            for (int p = 1; p < 8; p++) add2(ss, red[p * 256 + tid]);
            float2 f = unp2(ss);  // (j0, j0+1) @ b=ebB
            float n0 = tanhf(f.x + xpB.x);
            float n1 = tanhf(f.y + xpB.y);
            hdst[jB0 * 64 + ebB]       = (1.f - z0) * h0 + z0 * n0;
            hdst[(jB0 + 1) * 64 + ebB] = (1.f - z1) * h1 + z1 * n1;
        }
        gridbar();
    }
}

// -------- head: out[b][o] = sum_k hT[0][k][b] * Wf[k][o] + bf[o] --------
__global__ void head_kernel(const float* __restrict__ Wf,
                            const float* __restrict__ bf,
                            float* __restrict__ out) {
    const int b = blockIdx.x, o = threadIdx.x;
    const float* h = d_hT[0];   // after 512 steps, final h lives in buffer 0
    float acc = bf[o];
#pragma unroll 8
    for (int k = 0; k < 1024; k++)
        acc += h[k * 64 + b] * Wf[(size_t)k * 256 + o];
    out[b * 256 + o] = acc;
}

extern "C" void kernel_launch(void* const* d_in, const int* in_sizes, int n_in,
                              void* d_out, int out_size) {
    const float* x   = (const float*)d_in[0];
    const float* Wxz = (const float*)d_in[1];
    const float* Whz = (const float*)d_in[2];
    const float* Wxr = (const float*)d_in[3];
    const float* Whr = (const float*)d_in[4];
    const float* Wxh = (const float*)d_in[5];
    const float* Whh = (const float*)d_in[6];
    const float* bz  = (const float*)d_in[7];
    const float* br  = (const float*)d_in[8];
    const float* bh  = (const float*)d_in[9];
    const float* Wf  = (const float*)d_in[10];
    const float* bf  = (const float*)d_in[11];
    float* out = (float*)d_out;

    dim3 gx(48, 512);
    xproj_kernel<<<gx, 256>>>(x, Wxz, Wxr, Wxh, bz, br, bh);
    cudaFuncSetAttribute(gru_kernel, cudaFuncAttributeMaxDynamicSharedMemorySize, SMEM_BYTES);
    gru_kernel<<<NBLK, NTHR, SMEM_BYTES>>>(Whz, Whr, Whh);
    head_kernel<<<64, 256>>>(Wf, bf, out);
}

// round 5
// speedup vs baseline: 1.5103x; 1.0011x over previous
#include <cuda_runtime.h>
#include <cstdint>

// GRU: B=64, S=512, I=256, H=1024, O=256.
//   1) xproj_kernel: XP[b*512+s][3072] = x_bs @ [Wxz|Wxr|Wxh] + [bz|br|bh]
//   2) gru_kernel (persistent, 128 blocks, monotone-counter grid barrier):
//        phase A -> z = sigmoid(.) (blocks 0-63), rh = sigmoid(.)*h (blocks 64-127)
//        phase B -> n = tanh(.), h_new = (1-z)h + z n
//      Weights resident in smem (96KB, native [k][col] layout -> col-pairs
//      pre-packed for fma.rn.f32x2). h/rh chunks double-buffered through smem.
//   3) head_kernel: out = h_final @ Wf + bf

#define NBLK 128
#define NTHR 256
#define Bv 64
#define Sv 512
#define Hv 1024

typedef unsigned long long u64;

// -------- device scratch --------
__device__ float d_XP[(size_t)Bv * Sv * 3072];   // 402 MB x-projections (+bias)
__device__ float d_hT[2][Hv * Bv];               // h transposed [k][b], double buffered
__device__ float d_zT[Hv * Bv];                  // z transposed [j][b]
__device__ float d_rhT[Hv * Bv];                 // (r*h) transposed [k][b]
__device__ unsigned d_count;                      // monotone barrier counter

// -------- f32x2 helpers --------
__device__ __forceinline__ u64 dup2(float x) {
    u64 r; asm("mov.b64 %0, {%1, %1};" : "=l"(r) : "f"(x)); return r;
}
__device__ __forceinline__ void fma2(u64& a, u64 x, u64 y) {
    asm("fma.rn.f32x2 %0, %1, %2, %0;" : "+l"(a) : "l"(x), "l"(y));
}
__device__ __forceinline__ void add2(u64& a, u64 x) {
    asm("add.rn.f32x2 %0, %1, %0;" : "+l"(a) : "l"(x));
}
__device__ __forceinline__ float2 unp2(u64 v) {
    float2 f; asm("mov.b64 {%0, %1}, %2;" : "=f"(f.x), "=f"(f.y) : "l"(v)); return f;
}
__device__ __forceinline__ void lds128(u64& a, u64& b, unsigned addr) {
    asm volatile("ld.shared.v2.u64 {%0, %1}, [%2];" : "=l"(a), "=l"(b) : "r"(addr));
}
__device__ __forceinline__ float sigmoidf(float x) { return 1.f / (1.f + __expf(-x)); }

// -------- monotone grid barrier (replay-safe, no reset) --------
__device__ __forceinline__ void gridbar() {
    __syncthreads();
    if (threadIdx.x == 0) {
        __threadfence();
        unsigned a = atomicAdd(&d_count, 1u);
        unsigned target = a - (a & (NBLK - 1)) + NBLK;
        unsigned cur;
        do {
            asm volatile("ld.acquire.gpu.u32 %0, [%1];" : "=r"(cur) : "l"(&d_count));
        } while ((int)(cur - target) < 0);
    }
    __syncthreads();
}

// -------- x-projection GEMM (unchanged from passing R2 kernel) --------
__global__ void __launch_bounds__(256) xproj_kernel(
    const float* __restrict__ x,
    const float* __restrict__ Wxz, const float* __restrict__ Wxr, const float* __restrict__ Wxh,
    const float* __restrict__ bz,  const float* __restrict__ br,  const float* __restrict__ bh) {
    __shared__ float As[64 * 68];
    __shared__ float Bs[64 * 68];
    const int tid = threadIdx.x;
    const int ct = blockIdx.x, rt = blockIdx.y;
    const int wsel = ct >> 4;
    const float* W    = (wsel == 0) ? Wxz : ((wsel == 1) ? Wxr : Wxh);
    const float* bias = (wsel == 0) ? bz  : ((wsel == 1) ? br  : bh);
    const int colbase = (ct & 15) * 64;
    const int row0 = rt * 64;
    const int r4 = (tid >> 4) * 4, c4 = (tid & 15) * 4;

    u64 acc[4][2] = {};
    for (int k0 = 0; k0 < 256; k0 += 64) {
        __syncthreads();
#pragma unroll
        for (int i = 0; i < 4; i++) {
            int q = tid + i * 256; int rr = q >> 4, kq = q & 15;
            *(float4*)&As[rr * 68 + kq * 4] =
                *(const float4*)&x[(size_t)(row0 + rr) * 256 + k0 + kq * 4];
        }
#pragma unroll
        for (int i = 0; i < 4; i++) {
            int q = tid + i * 256; int kk = q >> 4, cq = q & 15;
            *(float4*)&Bs[kk * 68 + cq * 4] =
                *(const float4*)&W[(size_t)(k0 + kk) * 1024 + colbase + cq * 4];
        }
        __syncthreads();
        unsigned bs_u = (unsigned)__cvta_generic_to_shared(&Bs[c4]);
#pragma unroll 8
        for (int kk = 0; kk < 64; kk++) {
            u64 bLo, bHi; lds128(bLo, bHi, bs_u + kk * 68 * 4);
#pragma unroll
            for (int i = 0; i < 4; i++) {
                u64 ad = dup2(As[(r4 + i) * 68 + kk]);
                fma2(acc[i][0], ad, bLo);
                fma2(acc[i][1], ad, bHi);
            }
        }
    }
    float4 bb = *(const float4*)&bias[colbase + c4];
#pragma unroll
    for (int i = 0; i < 4; i++) {
        float2 lo = unp2(acc[i][0]), hi = unp2(acc[i][1]);
        float4 o = make_float4(lo.x + bb.x, lo.y + bb.y, hi.x + bb.z, hi.y + bb.w);
        *(float4*)&d_XP[(size_t)(row0 + r4 + i) * 3072 + ct * 64 + c4] = o;
    }
}

// -------- GEMM phase: stream 1024x64 activations through double-buffered smem --------
// COLS: weight row width (16 for phase A, 8 for B). KPT: k per thread per chunk.
template<int COLS, int KPT>
__device__ __forceinline__ void gemm_phase(
    const float* __restrict__ src,   // [1024][64] in global (ldcg)
    unsigned ws_su,                  // shared addr of weight tile base
    float* __restrict__ hbuf,        // shared, 2 x 8192 floats
    int tid, int kq, int cg, int b0,
    u64 acc01[4], u64 acc23[4])
{
    float4 rg[8];
#pragma unroll
    for (int i = 0; i < 8; i++) {
        int q = tid + i * NTHR;
        rg[i] = __ldcg((const float4*)&src[(q >> 4) * 64 + (q & 15) * 4]);
    }
#pragma unroll
    for (int i = 0; i < 8; i++) {
        int q = tid + i * NTHR;
        *(float4*)&hbuf[(q >> 4) * 64 + (q & 15) * 4] = rg[i];
    }
    __syncthreads();
#pragma unroll 1
    for (int t = 0; t < 8; t++) {
        if (t < 7) {
            const float* sp = src + (t + 1) * 128 * 64;
#pragma unroll
            for (int i = 0; i < 8; i++) {
                int q = tid + i * NTHR;
                rg[i] = __ldcg((const float4*)&sp[(q >> 4) * 64 + (q & 15) * 4]);
            }
        }
        unsigned wb = ws_su + (unsigned)(((t * 128 + kq * KPT) * COLS + cg * 4) * 4);
        const float4* hp = (const float4*)(hbuf + (t & 1) * 8192 + kq * KPT * 64 + b0);
#pragma unroll
        for (int j = 0; j < KPT; j++) {
            u64 w01, w23;
            lds128(w01, w23, wb + j * COLS * 4);
            float4 h4 = hp[j * 16];
            u64 hd;
            hd = dup2(h4.x); fma2(acc01[0], w01, hd); fma2(acc23[0], w23, hd);
            hd = dup2(h4.y); fma2(acc01[1], w01, hd); fma2(acc23[1], w23, hd);
            hd = dup2(h4.z); fma2(acc01[2], w01, hd); fma2(acc23[2], w23, hd);
            hd = dup2(h4.w); fma2(acc01[3], w01, hd); fma2(acc23[3], w23, hd);
        }
        if (t < 7) {
            float* db = hbuf + ((t + 1) & 1) * 8192;
#pragma unroll
            for (int i = 0; i < 8; i++) {
                int q = tid + i * NTHR;
                *(float4*)&db[(q >> 4) * 64 + (q & 15) * 4] = rg[i];
            }
        }
        __syncthreads();
    }
}

// -------- persistent GRU recurrence --------
// smem: wsA[1024][16] (64KB), wsB[1024][8] (32KB), hbuf[2][8192] (64KB), red[2048] u64 (16KB)
#define SMEM_BYTES ((16384 + 8192 + 16384) * 4 + 2048 * 8)

__global__ void __launch_bounds__(NTHR, 1) gru_kernel(
    const float* __restrict__ Whz, const float* __restrict__ Whr,
    const float* __restrict__ Whh)
{
    extern __shared__ float sm[];
    float* wsA  = sm;                    // [1024][16]
    float* wsB  = sm + 16384;            // [1024][8]
    float* hbuf = sm + 16384 + 8192;     // [2][8192]
    u64*   red  = (u64*)(sm + 16384 + 8192 + 16384);

    const int tid = threadIdx.x, bid = blockIdx.x;
    const unsigned wsA_su = (unsigned)__cvta_generic_to_shared(wsA);
    const unsigned wsB_su = (unsigned)__cvta_generic_to_shared(wsB);

    // ---- load block's weight slices into smem once (native [k][col] layout) ----
    const float* WA = (bid < 64) ? (Whz + bid * 16) : (Whr + (bid - 64) * 16);
#pragma unroll
    for (int i = 0; i < 16; i++) {
        int q = tid + i * NTHR; int k = q >> 2, c = q & 3;
        *(float4*)&wsA[k * 16 + c * 4] = __ldg((const float4*)&WA[(size_t)k * 1024 + c * 4]);
    }
#pragma unroll
    for (int i = 0; i < 8; i++) {
        int q = tid + i * NTHR; int k = q >> 1, c = q & 1;
        *(float4*)&wsB[k * 8 + c * 4] = __ldg((const float4*)&Whh[(size_t)k * 1024 + bid * 8 + c * 4]);
    }

    // ---- zero h0 across the grid ----
    ((float2*)d_hT[0])[bid * NTHR + tid] = make_float2(0.f, 0.f);
    gridbar();

    // thread mappings
    const int kqA = tid >> 6, cgA = (tid >> 4) & 3;
    const int g = tid & 15, b0 = g * 4;
    const int kqB = tid >> 5, cgB = (tid >> 4) & 1;
    // epilogue A: two consecutive b for col-pair
    const int ecpA = tid >> 5;              // col-pair 0..7
    const int ebA  = (tid * 2) & 63;        // even b
    const int cA0  = bid * 16 + ecpA * 2;   // global col in [0,2048)
    // epilogue B
    const int ecpB = tid >> 6;              // 0..3
    const int ebB  = tid & 63;
    const int jB0  = bid * 8 + ecpB * 2;

    for (int s = 0; s < Sv; s++) {
        const float* hsrc = d_hT[s & 1];
        float* hdst = d_hT[(s & 1) ^ 1];

        // ================= Phase A =================
        // prefetch epilogue operands
        float2 xpA0 = __ldg((const float2*)&d_XP[((size_t)ebA * 512 + s) * 3072 + cA0]);
        float2 xpA1 = __ldg((const float2*)&d_XP[((size_t)(ebA + 1) * 512 + s) * 3072 + cA0]);
        float2 hA0 = make_float2(0.f, 0.f), hA1 = hA0;
        if (bid >= 64) {
            hA0 = __ldcg((const float2*)&hsrc[(cA0 - 1024) * 64 + ebA]);
            hA1 = __ldcg((const float2*)&hsrc[(cA0 - 1023) * 64 + ebA]);
        }

        u64 a01[4] = {0, 0, 0, 0}, a23[4] = {0, 0, 0, 0};
        gemm_phase<16, 32>(hsrc, wsA_su, hbuf, tid, kqA, cgA, b0, a01, a23);

        {
            u64* rp = red + kqA * 512 + (cgA * 2) * 64 + b0;
#pragma unroll
            for (int bj = 0; bj < 4; bj++) { rp[bj] = a01[bj]; rp[64 + bj] = a23[bj]; }
        }
        __syncthreads();
        {
            int idx = tid * 2;
            u64 s0 = red[idx], s1 = red[idx + 1];
#pragma unroll
            for (int p = 1; p < 4; p++) {
                add2(s0, red[p * 512 + idx]);
                add2(s1, red[p * 512 + idx + 1]);
            }
            float2 f0 = unp2(s0), f1 = unp2(s1);  // f0: (c0,c1) @ b=ebA ; f1: @ b=ebA+1
            float v00 = sigmoidf(f0.x + xpA0.x), v01 = sigmoidf(f0.y + xpA0.y);
            float v10 = sigmoidf(f1.x + xpA1.x), v11 = sigmoidf(f1.y + xpA1.y);
            if (bid < 64) {
                *(float2*)&d_zT[cA0 * 64 + ebA]       = make_float2(v00, v10);
                *(float2*)&d_zT[(cA0 + 1) * 64 + ebA] = make_float2(v01, v11);
            } else {
                int j0 = cA0 - 1024;
                *(float2*)&d_rhT[j0 * 64 + ebA]       = make_float2(v00 * hA0.x, v10 * hA0.y);
                *(float2*)&d_rhT[(j0 + 1) * 64 + ebA] = make_float2(v01 * hA1.x, v11 * hA1.y);
            }
        }
        gridbar();

        // ================= Phase B =================
        float2 xpB = __ldg((const float2*)&d_XP[((size_t)ebB * 512 + s) * 3072 + 2048 + jB0]);
        float z0 = __ldcg(&d_zT[jB0 * 64 + ebB]);
        float z1 = __ldcg(&d_zT[(jB0 + 1) * 64 + ebB]);
        float h0 = __ldcg(&hsrc[jB0 * 64 + ebB]);
        float h1 = __ldcg(&hsrc[(jB0 + 1) * 64 + ebB]);

        u64 n01[4] = {0, 0, 0, 0}, n23[4] = {0, 0, 0, 0};
        gemm_phase<8, 16>(d_rhT, wsB_su, hbuf, tid, kqB, cgB, b0, n01, n23);

        {
            u64* rp = red + kqB * 256 + (cgB * 2) * 64 + b0;
#pragma unroll
            for (int bj = 0; bj < 4; bj++) { rp[bj] = n01[bj]; rp[64 + bj] = n23[bj]; }
        }
        __syncthreads();
        {
            u64 ss = red[tid];
#pragma unroll
            for (int p = 1; p < 8; p++) add2(ss, red[p * 256 + tid]);
            float2 f = unp2(ss);  // (j0, j0+1) @ b=ebB
            float n0 = tanhf(f.x + xpB.x);
            float n1 = tanhf(f.y + xpB.y);
            hdst[jB0 * 64 + ebB]       = (1.f - z0) * h0 + z0 * n0;
            hdst[(jB0 + 1) * 64 + ebB] = (1.f - z1) * h1 + z1 * n1;
        }
        gridbar();
    }
}

// -------- head: out[b][o] = sum_k hT[0][k][b] * Wf[k][o] + bf[o] --------
__global__ void head_kernel(const float* __restrict__ Wf,
                            const float* __restrict__ bf,
                            float* __restrict__ out) {
    const int b = blockIdx.x, o = threadIdx.x;
    const float* h = d_hT[0];   // after 512 steps, final h lives in buffer 0
    float acc = bf[o];
#pragma unroll 8
    for (int k = 0; k < 1024; k++)
        acc += h[k * 64 + b] * Wf[(size_t)k * 256 + o];
    out[b * 256 + o] = acc;
}

extern "C" void kernel_launch(void* const* d_in, const int* in_sizes, int n_in,
                              void* d_out, int out_size) {
    const float* x   = (const float*)d_in[0];
    const float* Wxz = (const float*)d_in[1];
    const float* Whz = (const float*)d_in[2];
    const float* Wxr = (const float*)d_in[3];
    const float* Whr = (const float*)d_in[4];
    const float* Wxh = (const float*)d_in[5];
    const float* Whh = (const float*)d_in[6];
    const float* bz  = (const float*)d_in[7];
    const float* br  = (const float*)d_in[8];
    const float* bh  = (const float*)d_in[9];
    const float* Wf  = (const float*)d_in[10];
    const float* bf  = (const float*)d_in[11];
    float* out = (float*)d_out;

    dim3 gx(48, 512);
    xproj_kernel<<<gx, 256>>>(x, Wxz, Wxr, Wxh, bz, br, bh);
    cudaFuncSetAttribute(gru_kernel, cudaFuncAttributeMaxDynamicSharedMemorySize, SMEM_BYTES);
    gru_kernel<<<NBLK, NTHR, SMEM_BYTES>>>(Whz, Whr, Whh);
    head_kernel<<<64, 256>>>(Wf, bf, out);
}

// round 7
// speedup vs baseline: 2.2590x; 1.4957x over previous
#include <cuda_runtime.h>
#include <cuda_bf16.h>
#include <cstdint>

#define NBLK 128
#define NTHR 256
typedef unsigned u32;
typedef unsigned long long u64;

// -------- device scratch --------
__device__ float d_XP[(size_t)64 * 512 * 3072];   // x-projections (+bias) [b*512+s][3072]
__device__ float d_hF[2][1024 * 64];              // h fp32 [col][b], double buffered
__device__ float d_z[1024 * 64];                  // z fp32 [col][b]
__device__ unsigned short d_hHi[64 * 1024], d_hLo[64 * 1024];    // h split bf16 [b][k]
__device__ unsigned short d_rhHi[64 * 1024], d_rhLo[64 * 1024];  // r*h split bf16 [b][k]
__device__ float d_pA[(size_t)8 * 2048 * 64];     // phase-A partials [p][col][b]
__device__ float d_pB[(size_t)16 * 1024 * 64];    // phase-B partials [p][col][b]
__device__ unsigned d_count;

// -------- helpers --------
__device__ __forceinline__ u64 dup2(float x){u64 r;asm("mov.b64 %0,{%1,%1};":"=l"(r):"f"(x));return r;}
__device__ __forceinline__ void fma2(u64&a,u64 x,u64 y){asm("fma.rn.f32x2 %0,%1,%2,%0;":"+l"(a):"l"(x),"l"(y));}
__device__ __forceinline__ float2 unp2(u64 v){float2 f;asm("mov.b64 {%0,%1},%2;":"=f"(f.x),"=f"(f.y):"l"(v));return f;}
__device__ __forceinline__ void lds128(u64&a,u64&b,unsigned ad){asm volatile("ld.shared.v2.u64 {%0,%1},[%2];":"=l"(a),"=l"(b):"r"(ad));}
__device__ __forceinline__ float sigmoidf(float x){return 1.f/(1.f+__expf(-x));}

__device__ __forceinline__ void mma_bf16(float* c,const u32* a,const u32* b){
    asm volatile("mma.sync.aligned.m16n8k16.row.col.f32.bf16.bf16.f32 "
        "{%0,%1,%2,%3},{%4,%5,%6,%7},{%8,%9},{%0,%1,%2,%3};"
        : "+f"(c[0]),"+f"(c[1]),"+f"(c[2]),"+f"(c[3])
        : "r"(a[0]),"r"(a[1]),"r"(a[2]),"r"(a[3]),"r"(b[0]),"r"(b[1]));
}
__device__ __forceinline__ unsigned short bfhi(float x){
    return __bfloat16_as_ushort(__float2bfloat16(x));
}
__device__ __forceinline__ unsigned short bflo(float x){
    float h=__bfloat162float(__float2bfloat16(x));
    return __bfloat16_as_ushort(__float2bfloat16(x-h));
}

__device__ __forceinline__ void gridbar(){
    __syncthreads();
    if(threadIdx.x==0){
        __threadfence();
        unsigned a=atomicAdd(&d_count,1u);
        unsigned tg=a-(a&(NBLK-1))+NBLK,cur;
        do{asm volatile("ld.acquire.gpu.u32 %0,[%1];":"=r"(cur):"l"(&d_count));}while((int)(cur-tg)<0);
    }
    __syncthreads();
}

// -------- xproj (fp32, proven) --------
__global__ void __launch_bounds__(256) xproj_kernel(
    const float* __restrict__ x,
    const float* __restrict__ Wxz,const float* __restrict__ Wxr,const float* __restrict__ Wxh,
    const float* __restrict__ bz,const float* __restrict__ br,const float* __restrict__ bh){
    __shared__ float As[64*68],Bs[64*68];
    const int tid=threadIdx.x,ct=blockIdx.x,rt=blockIdx.y,wsel=ct>>4;
    const float* W=(wsel==0)?Wxz:((wsel==1)?Wxr:Wxh);
    const float* bias=(wsel==0)?bz:((wsel==1)?br:bh);
    const int colbase=(ct&15)*64,row0=rt*64,r4=(tid>>4)*4,c4=(tid&15)*4;
    u64 acc[4][2]={};
    for(int k0=0;k0<256;k0+=64){
        __syncthreads();
#pragma unroll
        for(int i=0;i<4;i++){int q=tid+i*256,rr=q>>4,kq=q&15;
            *(float4*)&As[rr*68+kq*4]=*(const float4*)&x[(size_t)(row0+rr)*256+k0+kq*4];}
#pragma unroll
        for(int i=0;i<4;i++){int q=tid+i*256,kk=q>>4,cq=q&15;
            *(float4*)&Bs[kk*68+cq*4]=*(const float4*)&W[(size_t)(k0+kk)*1024+colbase+cq*4];}
        __syncthreads();
        unsigned bs=(unsigned)__cvta_generic_to_shared(&Bs[c4]);
#pragma unroll 8
        for(int kk=0;kk<64;kk++){
            u64 bL,bH;lds128(bL,bH,bs+kk*68*4);
#pragma unroll
            for(int i=0;i<4;i++){u64 ad=dup2(As[(r4+i)*68+kk]);fma2(acc[i][0],ad,bL);fma2(acc[i][1],ad,bH);}
        }
    }
    float4 bb=*(const float4*)&bias[colbase+c4];
#pragma unroll
    for(int i=0;i<4;i++){
        float2 lo=unp2(acc[i][0]),hi=unp2(acc[i][1]);
        *(float4*)&d_XP[(size_t)(row0+r4+i)*3072+ct*64+c4]=make_float4(lo.x+bb.x,lo.y+bb.y,hi.x+bb.z,hi.y+bb.w);
    }
}

// -------- persistent GRU: HMMA split-bf16, K split across blocks --------
// smem (u16 units): WA hi/lo [64][264], WB hi/lo [64][136], ST hi/lo [64][264]
#define WAHI 0
#define WALO 16896
#define WBHI 33792
#define WBLO 42496
#define STHI 51200
#define STLO 68096
#define SMEM_BYTES (84992*2)

__global__ void __launch_bounds__(NTHR,1) gru_kernel(
    const float* __restrict__ Whz,const float* __restrict__ Whr,const float* __restrict__ Whh){
    extern __shared__ unsigned short sm[];
    const int tid=threadIdx.x,bid=blockIdx.x,wid=tid>>5,lane=tid&31;
    const int cg=bid&31, kg=bid>>5;    // phase A: 32 col-groups x 4 k-groups(256)
    const int cgB=bid&15,kgB=bid>>4;   // phase B: 16 col-groups x 8 k-groups(128)

    // ---- load resident weight slices (split bf16, [col][k]+pad) ----
    {
        const int colg0=cg*64;
        const float* W=(colg0<1024)?(Whz+colg0):(Whr+colg0-1024);
#pragma unroll 4
        for(int i=0;i<64;i++){
            int idx=tid+i*NTHR,col=idx&63,k=idx>>6;
            float w=__ldg(&W[(size_t)(kg*256+k)*1024+col]);
            sm[WAHI+col*264+k]=bfhi(w);
            sm[WALO+col*264+k]=bflo(w);
        }
#pragma unroll 4
        for(int i=0;i<32;i++){
            int idx=tid+i*NTHR,col=idx&63,k=idx>>6;
            float w=__ldg(&Whh[(size_t)(kgB*128+k)*1024+cgB*64+col]);
            sm[WBHI+col*136+k]=bfhi(w);
            sm[WBLO+col*136+k]=bflo(w);
        }
    }
    // ---- zero h0 state ----
    {
        int gid=bid*NTHR+tid;
        ((float2*)d_hF[0])[gid]=make_float2(0.f,0.f);
        ((u32*)d_hHi)[gid]=0;((u32*)d_hLo)[gid]=0;
    }
    gridbar();

    const int mw=wid&1,nw=(wid>>1)&1,kw=wid>>2;
    const int g=lane>>2,tk=(lane&3)*2;
    const int ecA=bid*16+wid*2;   // epilogue A: col pair
    const int eb=lane*2;          // epilogue: batch pair
    const int ecB=bid*8+wid;      // epilogue B: single col

    for(int s=0;s<512;s++){
        const int cur=s&1,nxt=cur^1;
        // prefetch epilogue-A operands
        float2 xpa=*(const float2*)&d_XP[((size_t)eb*512+s)*3072+ecA];
        float2 xpb=*(const float2*)&d_XP[((size_t)(eb+1)*512+s)*3072+ecA];
        float2 hp0=make_float2(0.f,0.f),hp1=hp0;
        if(bid>=64){
            hp0=__ldcg((const float2*)&d_hF[cur][(ecA-1024)*64+eb]);
            hp1=__ldcg((const float2*)&d_hF[cur][(ecA-1023)*64+eb]);
        }
        // ---- stage h slice (kg*256) ----
#pragma unroll
        for(int i=0;i<8;i++){
            int u=tid+i*NTHR,b=u>>5,ko=u&31;
            uint4 v=__ldcg((const uint4*)&d_hHi[(size_t)b*1024+kg*256+ko*8]);
            *(uint4*)&sm[STHI+b*264+ko*8]=v;
            uint4 w=__ldcg((const uint4*)&d_hLo[(size_t)b*1024+kg*256+ko*8]);
            *(uint4*)&sm[STLO+b*264+ko*8]=w;
        }
        __syncthreads();
        // ---- phase A MMA: warp m32n32, k-slice kw*128 ----
        float c[2][4][4];
#pragma unroll
        for(int mt=0;mt<2;mt++)
#pragma unroll
        for(int nt=0;nt<4;nt++)
#pragma unroll
        for(int q=0;q<4;q++)c[mt][nt][q]=0.f;
#pragma unroll 1
        for(int i=0;i<8;i++){
            int kk=kw*128+i*16+tk;
            u32 ah[2][4],al[2][4],bh[4][2],bl[4][2];
#pragma unroll
            for(int mt=0;mt<2;mt++){
                int r=mw*32+mt*16+g;
                ah[mt][0]=*(const u32*)&sm[WAHI+r*264+kk];
                ah[mt][1]=*(const u32*)&sm[WAHI+(r+8)*264+kk];
                ah[mt][2]=*(const u32*)&sm[WAHI+r*264+kk+8];
                ah[mt][3]=*(const u32*)&sm[WAHI+(r+8)*264+kk+8];
                al[mt][0]=*(const u32*)&sm[WALO+r*264+kk];
                al[mt][1]=*(const u32*)&sm[WALO+(r+8)*264+kk];
                al[mt][2]=*(const u32*)&sm[WALO+r*264+kk+8];
                al[mt][3]=*(const u32*)&sm[WALO+(r+8)*264+kk+8];
            }
#pragma unroll
            for(int nt=0;nt<4;nt++){
                int b=nw*32+nt*8+g;
                bh[nt][0]=*(const u32*)&sm[STHI+b*264+kk];
                bh[nt][1]=*(const u32*)&sm[STHI+b*264+kk+8];
                bl[nt][0]=*(const u32*)&sm[STLO+b*264+kk];
                bl[nt][1]=*(const u32*)&sm[STLO+b*264+kk+8];
            }
#pragma unroll
            for(int mt=0;mt<2;mt++)
#pragma unroll
            for(int nt=0;nt<4;nt++){
                mma_bf16(c[mt][nt],ah[mt],bh[nt]);
                mma_bf16(c[mt][nt],ah[mt],bl[nt]);
                mma_bf16(c[mt][nt],al[mt],bh[nt]);
            }
        }
        {
            int p=kg*2+kw;
#pragma unroll
            for(int mt=0;mt<2;mt++){
                int col=cg*64+mw*32+mt*16+g;
#pragma unroll
                for(int nt=0;nt<4;nt++){
                    int b=nw*32+nt*8+tk;
                    *(float2*)&d_pA[((size_t)p*2048+col)*64+b]=make_float2(c[mt][nt][0],c[mt][nt][1]);
                    *(float2*)&d_pA[((size_t)p*2048+col+8)*64+b]=make_float2(c[mt][nt][2],c[mt][nt][3]);
                }
            }
        }
        gridbar();
        // ---- epilogue A: sum 8 partials -> sigmoid -> z or rh ----
        {
            float s0=0.f,s1=0.f,s2=0.f,s3=0.f;
#pragma unroll
            for(int p=0;p<8;p++){
                float2 v0=__ldcg((const float2*)&d_pA[((size_t)p*2048+ecA)*64+eb]);
                float2 v1=__ldcg((const float2*)&d_pA[((size_t)p*2048+ecA+1)*64+eb]);
                s0+=v0.x;s1+=v0.y;s2+=v1.x;s3+=v1.y;
            }
            float v00=sigmoidf(s0+xpa.x),v01=sigmoidf(s1+xpb.x);
            float v10=sigmoidf(s2+xpa.y),v11=sigmoidf(s3+xpb.y);
            if(bid<64){
                *(float2*)&d_z[ecA*64+eb]=make_float2(v00,v01);
                *(float2*)&d_z[(ecA+1)*64+eb]=make_float2(v10,v11);
            }else{
                int cp=ecA-1024;
                float r00=v00*hp0.x,r01=v01*hp0.y,r10=v10*hp1.x,r11=v11*hp1.y;
                *(u32*)&d_rhHi[(size_t)eb*1024+cp]    =(u32)bfhi(r00)|((u32)bfhi(r10)<<16);
                *(u32*)&d_rhHi[(size_t)(eb+1)*1024+cp]=(u32)bfhi(r01)|((u32)bfhi(r11)<<16);
                *(u32*)&d_rhLo[(size_t)eb*1024+cp]    =(u32)bflo(r00)|((u32)bflo(r10)<<16);
                *(u32*)&d_rhLo[(size_t)(eb+1)*1024+cp]=(u32)bflo(r01)|((u32)bflo(r11)<<16);
            }
        }
        gridbar();
        // prefetch epilogue-B operands
        float xq0=d_XP[((size_t)eb*512+s)*3072+2048+ecB];
        float xq1=d_XP[((size_t)(eb+1)*512+s)*3072+2048+ecB];
        float2 zv=__ldcg((const float2*)&d_z[ecB*64+eb]);
        float2 hv=__ldcg((const float2*)&d_hF[cur][ecB*64+eb]);
        // ---- stage rh slice (kgB*128) ----
#pragma unroll
        for(int i=0;i<4;i++){
            int u=tid+i*NTHR,b=u>>4,ko=u&15;
            uint4 v=__ldcg((const uint4*)&d_rhHi[(size_t)b*1024+kgB*128+ko*8]);
            *(uint4*)&sm[STHI+b*264+ko*8]=v;
            uint4 w=__ldcg((const uint4*)&d_rhLo[(size_t)b*1024+kgB*128+ko*8]);
            *(uint4*)&sm[STLO+b*264+ko*8]=w;
        }
        __syncthreads();
        // ---- phase B MMA: warp m32n32, k-slice kw*64 ----
        float cb[2][4][4];
#pragma unroll
        for(int mt=0;mt<2;mt++)
#pragma unroll
        for(int nt=0;nt<4;nt++)
#pragma unroll
        for(int q=0;q<4;q++)cb[mt][nt][q]=0.f;
#pragma unroll 1
        for(int i=0;i<4;i++){
            int kk=kw*64+i*16+tk;
            u32 ah[2][4],al[2][4],bh[4][2],bl[4][2];
#pragma unroll
            for(int mt=0;mt<2;mt++){
                int r=mw*32+mt*16+g;
                ah[mt][0]=*(const u32*)&sm[WBHI+r*136+kk];
                ah[mt][1]=*(const u32*)&sm[WBHI+(r+8)*136+kk];
                ah[mt][2]=*(const u32*)&sm[WBHI+r*136+kk+8];
                ah[mt][3]=*(const u32*)&sm[WBHI+(r+8)*136+kk+8];
                al[mt][0]=*(const u32*)&sm[WBLO+r*136+kk];
                al[mt][1]=*(const u32*)&sm[WBLO+(r+8)*136+kk];
                al[mt][2]=*(const u32*)&sm[WBLO+r*136+kk+8];
                al[mt][3]=*(const u32*)&sm[WBLO+(r+8)*136+kk+8];
            }
#pragma unroll
            for(int nt=0;nt<4;nt++){
                int b=nw*32+nt*8+g;
                bh[nt][0]=*(const u32*)&sm[STHI+b*264+kk];
                bh[nt][1]=*(const u32*)&sm[STHI+b*264+kk+8];
                bl[nt][0]=*(const u32*)&sm[STLO+b*264+kk];
                bl[nt][1]=*(const u32*)&sm[STLO+b*264+kk+8];
            }
#pragma unroll
            for(int mt=0;mt<2;mt++)
#pragma unroll
            for(int nt=0;nt<4;nt++){
                mma_bf16(cb[mt][nt],ah[mt],bh[nt]);
                mma_bf16(cb[mt][nt],ah[mt],bl[nt]);
                mma_bf16(cb[mt][nt],al[mt],bh[nt]);
            }
        }
        {
            int p=kgB*2+kw;
#pragma unroll
            for(int mt=0;mt<2;mt++){
                int col=cgB*64+mw*32+mt*16+g;
#pragma unroll
                for(int nt=0;nt<4;nt++){
                    int b=nw*32+nt*8+tk;
                    *(float2*)&d_pB[((size_t)p*1024+col)*64+b]=make_float2(cb[mt][nt][0],cb[mt][nt][1]);
                    *(float2*)&d_pB[((size_t)p*1024+col+8)*64+b]=make_float2(cb[mt][nt][2],cb[mt][nt][3]);
                }
            }
        }
        gridbar();
        // ---- epilogue B: sum 16 partials -> tanh -> h update ----
        {
            float s0=0.f,s1=0.f;
#pragma unroll
            for(int p=0;p<16;p++){
                float2 v=__ldcg((const float2*)&d_pB[((size_t)p*1024+ecB)*64+eb]);
                s0+=v.x;s1+=v.y;
            }
            float n0=tanhf(s0+xq0),n1=tanhf(s1+xq1);
            float h0=(1.f-zv.x)*hv.x+zv.x*n0;
            float h1=(1.f-zv.y)*hv.y+zv.y*n1;
            *(float2*)&d_hF[nxt][ecB*64+eb]=make_float2(h0,h1);
            d_hHi[(size_t)eb*1024+ecB]=bfhi(h0);
            d_hHi[(size_t)(eb+1)*1024+ecB]=bfhi(h1);
            d_hLo[(size_t)eb*1024+ecB]=bflo(h0);
            d_hLo[(size_t)(eb+1)*1024+ecB]=bflo(h1);
        }
        gridbar();
    }
}

// -------- head: out[b][o] = sum_k hF[0][k][b]*Wf[k][o] + bf[o] --------
__global__ void head_kernel(const float* __restrict__ Wf,const float* __restrict__ bf,float* __restrict__ out){
    const int b=blockIdx.x,o=threadIdx.x;
    const float* h=d_hF[0];   // after 512 steps final h is in buffer 0
    float acc=bf[o];
#pragma unroll 8
    for(int k=0;k<1024;k++)acc+=h[k*64+b]*Wf[(size_t)k*256+o];
    out[b*256+o]=acc;
}

extern "C" void kernel_launch(void* const* d_in,const int* in_sizes,int n_in,
                              void* d_out,int out_size){
    const float* x  =(const float*)d_in[0];
    const float* Wxz=(const float*)d_in[1];
    const float* Whz=(const float*)d_in[2];
    const float* Wxr=(const float*)d_in[3];
    const float* Whr=(const float*)d_in[4];
    const float* Wxh=(const float*)d_in[5];
    const float* Whh=(const float*)d_in[6];
    const float* bz =(const float*)d_in[7];
    const float* br =(const float*)d_in[8];
    const float* bh =(const float*)d_in[9];
    const float* Wf =(const float*)d_in[10];
    const float* bf =(const float*)d_in[11];
    float* out=(float*)d_out;

    dim3 gx(48,512);
    xproj_kernel<<<gx,256>>>(x,Wxz,Wxr,Wxh,bz,br,bh);
    cudaFuncSetAttribute(gru_kernel,cudaFuncAttributeMaxDynamicSharedMemorySize,SMEM_BYTES);
    gru_kernel<<<NBLK,NTHR,SMEM_BYTES>>>(Whz,Whr,Whh);
    head_kernel<<<64,256>>>(Wf,bf,out);
}